// round 15
// baseline (speedup 1.0000x reference)
#include <cuda_runtime.h>
#include <math.h>

#define NB 100000
#define NT 6            // 2 batches x 3 classes
#define NPRE 512
#define NPOST 100
#define SCORE_TH 0.1f
#define NMS_TH 0.25f
#define CAND_CAP 4096
#define SCAN_BLOCKS ((NB + 255) / 256)

// ---------------- scratch (static device globals; no allocation) -------------
__device__ float         g_scores[NT * NB];
__device__ unsigned      g_hist[NT][256];
__device__ unsigned      g_prefix[NT];
__device__ unsigned      g_krem[NT];
__device__ unsigned long long g_cand[NT][CAND_CAP];
__device__ unsigned      g_candCnt[NT];
__device__ int           g_topIdx[NT][NPRE];
__device__ float         g_topScore[NT][NPRE];

struct Prep {
    float cx[4], cy[4];
    float z0, z1, vol, pad;
};
__device__ Prep          g_prep[NT][NPRE];
__device__ unsigned      g_mask[NT][NPRE][NPRE / 32];
__device__ unsigned char g_keep[NT][NPRE];

// monotone float -> uint key
__device__ __forceinline__ unsigned fkey(float f) {
    unsigned u = __float_as_uint(f);
    return (u & 0x80000000u) ? ~u : (u | 0x80000000u);
}
__device__ __forceinline__ float finv(unsigned k) {
    return __uint_as_float((k & 0x80000000u) ? (k ^ 0x80000000u) : ~k);
}

// ---------------- kernels ----------------------------------------------------

__global__ void k_init() {
    int t = blockIdx.x;
    for (int i = threadIdx.x; i < 256; i += blockDim.x) g_hist[t][i] = 0;
    if (threadIdx.x == 0) {
        g_prefix[t]  = 0;
        g_krem[t]    = NPRE;
        g_candCnt[t] = 0;
    }
}

// compute sigmoid scores + histogram of top byte (radix pass 0)
__global__ void k_score_hist0(const float* __restrict__ cls) {
    int t = blockIdx.y;
    int b = t / 3, k = t % 3;
    __shared__ unsigned sh[256];
    if (threadIdx.x < 256) sh[threadIdx.x] = 0;
    __syncthreads();
    int i = blockIdx.x * blockDim.x + threadIdx.x;
    if (i < NB) {
        float x = cls[((size_t)b * NB + i) * 3 + k];
        float s = 1.0f / (1.0f + expf(-x));
        if (s < SCORE_TH) s = -1.0f;
        g_scores[(size_t)t * NB + i] = s;
        atomicAdd(&sh[fkey(s) >> 24], 1u);
    }
    __syncthreads();
    if (threadIdx.x < 256 && sh[threadIdx.x])
        atomicAdd(&g_hist[t][threadIdx.x], sh[threadIdx.x]);
}

// pick digit of current radix pass; update prefix & remaining-k; zero hist
__global__ void k_select(int shift) {
    int t = blockIdx.x;
    if (threadIdx.x == 0) {
        unsigned krem = g_krem[t];
        unsigned c = 0;
        for (int d = 255; d >= 0; --d) {
            unsigned h = g_hist[t][d];
            if (c + h >= krem) {
                g_krem[t]   = krem - c;
                g_prefix[t] |= ((unsigned)d) << shift;
                break;
            }
            c += h;
        }
    }
    __syncthreads();
    for (int i = threadIdx.x; i < 256; i += blockDim.x) g_hist[t][i] = 0;
}

// histogram of byte at `shift` restricted to elements matching the prefix
__global__ void k_hist(int shift) {
    int t = blockIdx.y;
    __shared__ unsigned sh[256];
    if (threadIdx.x < 256) sh[threadIdx.x] = 0;
    __syncthreads();
    int i = blockIdx.x * blockDim.x + threadIdx.x;
    unsigned pm = 0xFFFFFFFFu << (shift + 8);
    unsigned pref = g_prefix[t];
    if (i < NB) {
        unsigned key = fkey(g_scores[(size_t)t * NB + i]);
        if ((key & pm) == pref) atomicAdd(&sh[(key >> shift) & 255u], 1u);
    }
    __syncthreads();
    if (threadIdx.x < 256 && sh[threadIdx.x])
        atomicAdd(&g_hist[t][threadIdx.x], sh[threadIdx.x]);
}

// gather every element with key >= exact 512th-largest key
__global__ void k_gather() {
    int t = blockIdx.y;
    int i = blockIdx.x * blockDim.x + threadIdx.x;
    if (i >= NB) return;
    unsigned key = fkey(g_scores[(size_t)t * NB + i]);
    if (key >= g_prefix[t]) {
        unsigned pos = atomicAdd(&g_candCnt[t], 1u);
        if (pos < CAND_CAP)
            g_cand[t][pos] = ((unsigned long long)key << 32) | (unsigned)(~i);
    }
}

// single-block bitonic sort of candidates; emit top-512 (value desc, idx asc);
// fused: gather boxes and precompute corners/z/volume
__global__ void k_sort_prep(const float* __restrict__ boxes) {
    int t = blockIdx.x;
    int b = t / 3;
    __shared__ unsigned long long arr[CAND_CAP];
    unsigned cnt = g_candCnt[t];
    if (cnt > CAND_CAP) cnt = CAND_CAP;
    for (int i = threadIdx.x; i < CAND_CAP; i += blockDim.x)
        arr[i] = (i < (int)cnt) ? g_cand[t][i] : 0ULL;
    __syncthreads();
    // ascending bitonic sort
    for (unsigned ksz = 2; ksz <= CAND_CAP; ksz <<= 1) {
        for (unsigned j = ksz >> 1; j > 0; j >>= 1) {
            for (unsigned i = threadIdx.x; i < CAND_CAP; i += blockDim.x) {
                unsigned ixj = i ^ j;
                if (ixj > i) {
                    unsigned long long va = arr[i], vb = arr[ixj];
                    bool up = ((i & ksz) == 0);
                    if ((up && va > vb) || (!up && va < vb)) {
                        arr[i] = vb; arr[ixj] = va;
                    }
                }
            }
            __syncthreads();
        }
    }
    if (threadIdx.x < NPRE) {
        int r = threadIdx.x;
        unsigned long long v = arr[CAND_CAP - 1 - r]; // r-th largest
        unsigned key = (unsigned)(v >> 32);
        int idx = (int)(~(unsigned)(v & 0xFFFFFFFFu));
        float sc = finv(key);
        g_topIdx[t][r]   = idx;
        g_topScore[t][r] = sc;
        const float* bx = boxes + ((size_t)b * NB + idx) * 7;
        float x = bx[0], y = bx[1], z = bx[2];
        float dx = bx[3], dy = bx[4], dz = bx[5], rot = bx[6];
        float c = cosf(rot), s = sinf(rot);
        float hx = 0.5f * dx, hy = 0.5f * dy;
        Prep p;
        p.cx[0] = x + hx * c - hy * s;  p.cy[0] = y + hx * s + hy * c;
        p.cx[1] = x - hx * c - hy * s;  p.cy[1] = y - hx * s + hy * c;
        p.cx[2] = x - hx * c + hy * s;  p.cy[2] = y - hx * s - hy * c;
        p.cx[3] = x + hx * c + hy * s;  p.cy[3] = y + hx * s - hy * c;
        p.z0 = z - 0.5f * dz;  p.z1 = z + 0.5f * dz;
        p.vol = dx * dy * dz;  p.pad = 0.f;
        g_prep[t][r] = p;
    }
}

// exact rotated-rect intersection via Sutherland–Hodgman quad clipping
__device__ bool iou_over(const Prep& a, const Prep& b) {
    float h = fminf(a.z1, b.z1) - fmaxf(a.z0, b.z0);
    if (h <= 0.0f) return false;
    float px[10], py[10], qx[10], qy[10];
    int n = 4;
#pragma unroll
    for (int v = 0; v < 4; v++) { px[v] = a.cx[v]; py[v] = a.cy[v]; }
#pragma unroll
    for (int e = 0; e < 4; e++) {
        if (n == 0) break;
        float ex = b.cx[e], ey = b.cy[e];
        float dx_ = b.cx[(e + 1) & 3] - ex;
        float dy_ = b.cy[(e + 1) & 3] - ey;
        int m = 0;
        float fx = px[n - 1], fy = py[n - 1];
        float dprev = dx_ * (fy - ey) - dy_ * (fx - ex);
        for (int v = 0; v < n; v++) {
            float cxv = px[v], cyv = py[v];
            float d = dx_ * (cyv - ey) - dy_ * (cxv - ex);
            if (dprev >= 0.0f) {
                if (d >= 0.0f) { qx[m] = cxv; qy[m] = cyv; m++; }
                else {
                    float tt = dprev / (dprev - d);
                    qx[m] = fx + tt * (cxv - fx);
                    qy[m] = fy + tt * (cyv - fy); m++;
                }
            } else if (d >= 0.0f) {
                float tt = dprev / (dprev - d);
                qx[m] = fx + tt * (cxv - fx);
                qy[m] = fy + tt * (cyv - fy); m++;
                qx[m] = cxv; qy[m] = cyv; m++;
            }
            fx = cxv; fy = cyv; dprev = d;
        }
        n = m;
        for (int v = 0; v < n; v++) { px[v] = qx[v]; py[v] = qy[v]; }
    }
    if (n < 3) return false;
    float area = 0.0f;
    for (int v = 0; v < n; v++) {
        int w = (v + 1 == n) ? 0 : v + 1;
        area += px[v] * py[w] - px[w] * py[v];
    }
    area = 0.5f * fabsf(area);
    float i3 = area * h;
    float iou = i3 / fmaxf(a.vol + b.vol - i3, 1e-8f);
    return iou > NMS_TH;
}

// mask[t][i][w]: bit j set if IoU(i, j) > thresh
__global__ void k_iou(void) {
    int t = blockIdx.y, i = blockIdx.x;
    __shared__ float sA[12];
    if (threadIdx.x < 12)
        sA[threadIdx.x] = ((const float*)&g_prep[t][i])[threadIdx.x];
    __syncthreads();
    const Prep& A = *(const Prep*)sA;
    int lane = threadIdx.x & 31, wp = threadIdx.x >> 5;
#pragma unroll
    for (int it = 0; it < NPRE / 64; ++it) {
        int j = it * 64 + wp * 32 + lane;
        Prep B = g_prep[t][j];
        bool over = iou_over(A, B);
        unsigned m = __ballot_sync(0xFFFFFFFFu, over);
        if (lane == 0) g_mask[t][i][(it * 64 + wp * 32) >> 5] = m;
    }
}

// greedy suppression scan: warp holds 512-bit suppression state
__global__ void k_nms(void) {
    int t = blockIdx.x;
    __shared__ unsigned smask[NPRE * (NPRE / 32)];
    __shared__ float sscore[NPRE];
    const unsigned* gm = (const unsigned*)g_mask[t];
    for (int i = threadIdx.x; i < NPRE * (NPRE / 32); i += blockDim.x)
        smask[i] = gm[i];
    for (int i = threadIdx.x; i < NPRE; i += blockDim.x)
        sscore[i] = g_topScore[t][i];
    __syncthreads();
    if (threadIdx.x < 32) {
        int lane = threadIdx.x;
        unsigned sup = 0;
        for (int i = 0; i < NPRE; i++) {
            unsigned supw = __shfl_sync(0xFFFFFFFFu, sup, i >> 5);
            bool kept = (sscore[i] >= SCORE_TH) && !((supw >> (i & 31)) & 1u);
            if (kept && lane < 16) sup |= smask[i * 16 + lane];
            if (lane == 0) g_keep[t][i] = kept ? 1 : 0;
        }
    }
}

// write final padded outputs: boxes | scores | labels (flattened, float32)
__global__ void k_out(const float* __restrict__ boxes, float* __restrict__ out) {
    int t = blockIdx.x, b = t / 3, k = t % 3;
    __shared__ short rank[NPRE];
    if (threadIdx.x == 0) {
        int r = 0;
        for (int i = 0; i < NPRE; i++)
            rank[i] = g_keep[t][i] ? (short)(r++) : (short)-1;
    }
    __syncthreads();
    const int TOTAL = 3 * NPOST;               // 300 per batch
    float* outB = out;                          // (B, 300, 7)
    float* outS = out + 2 * TOTAL * 7;          // (B, 300)
    float* outL = out + 2 * TOTAL * 7 + 2 * TOTAL; // (B, 300)
    int baseRow = b * TOTAL + k * NPOST;
    for (int i = threadIdx.x; i < NPOST * 7; i += blockDim.x)
        outB[baseRow * 7 + i] = 0.0f;
    for (int i = threadIdx.x; i < NPOST; i += blockDim.x) {
        outS[baseRow + i] = 0.0f;
        outL[baseRow + i] = 0.0f;
    }
    __syncthreads();
    for (int i = threadIdx.x; i < NPRE; i += blockDim.x) {
        int r = rank[i];
        if (r >= 0 && r < NPOST) {
            int idx = g_topIdx[t][i];
            const float* bx = boxes + ((size_t)b * NB + idx) * 7;
            float* ob = outB + (baseRow + r) * 7;
#pragma unroll
            for (int c = 0; c < 7; c++) ob[c] = bx[c];
            outS[baseRow + r] = g_topScore[t][i];
            outL[baseRow + r] = (float)(k + 1);
        }
    }
}

// ---------------- launch -----------------------------------------------------
extern "C" void kernel_launch(void* const* d_in, const int* in_sizes, int n_in,
                              void* d_out, int out_size) {
    const float* cls   = (const float*)d_in[0];
    const float* boxes = (const float*)d_in[1];
    float* out = (float*)d_out;

    dim3 gscan(SCAN_BLOCKS, NT);

    k_init<<<NT, 256>>>();
    k_score_hist0<<<gscan, 256>>>(cls);
    k_select<<<NT, 256>>>(24);
    k_hist<<<gscan, 256>>>(16);
    k_select<<<NT, 256>>>(16);
    k_hist<<<gscan, 256>>>(8);
    k_select<<<NT, 256>>>(8);
    k_hist<<<gscan, 256>>>(0);
    k_select<<<NT, 256>>>(0);
    k_gather<<<gscan, 256>>>();
    k_sort_prep<<<NT, 1024>>>(boxes);
    k_iou<<<dim3(NPRE, NT), 64>>>();
    k_nms<<<NT, 256>>>();
    k_out<<<NT, 128>>>(boxes, out);
}

// round 16
// speedup vs baseline: 1.0093x; 1.0093x over previous
#include <cuda_runtime.h>
#include <math.h>

#define NB 100000
#define NT 6            // 2 batches x 3 classes
#define NPRE 512
#define NPOST 100
#define SCORE_TH 0.1f
#define NMS_TH 0.25f
#define CAND_CAP 4096
#define SCAN_BLOCKS ((NB + 255) / 256)

// ---------------- scratch (static device globals; no allocation) -------------
__device__ float         g_scores[NT * NB];
__device__ unsigned      g_hist[NT][256];
__device__ unsigned      g_prefix[NT];
__device__ unsigned      g_krem[NT];
__device__ unsigned long long g_cand[NT][CAND_CAP];
__device__ unsigned      g_candCnt[NT];
__device__ int           g_topIdx[NT][NPRE];
__device__ float         g_topScore[NT][NPRE];

struct Prep {
    float cx[4], cy[4];
    float z0, z1, vol, pad;
};
__device__ Prep          g_prep[NT][NPRE];
__device__ unsigned      g_mask[NT][NPRE][NPRE / 32];
__device__ unsigned char g_keep[NT][NPRE];

// monotone float -> uint key
__device__ __forceinline__ unsigned fkey(float f) {
    unsigned u = __float_as_uint(f);
    return (u & 0x80000000u) ? ~u : (u | 0x80000000u);
}
__device__ __forceinline__ float finv(unsigned k) {
    return __uint_as_float((k & 0x80000000u) ? (k ^ 0x80000000u) : ~k);
}

// ---------------- kernels ----------------------------------------------------

__global__ void k_init() {
    int t = blockIdx.x;
    for (int i = threadIdx.x; i < 256; i += blockDim.x) g_hist[t][i] = 0;
    if (threadIdx.x == 0) {
        g_prefix[t]  = 0;
        g_krem[t]    = NPRE;
        g_candCnt[t] = 0;
    }
}

// compute sigmoid scores + histogram of top byte (radix pass 0)
__global__ void k_score_hist0(const float* __restrict__ cls) {
    int t = blockIdx.y;
    int b = t / 3, k = t % 3;
    __shared__ unsigned sh[256];
    if (threadIdx.x < 256) sh[threadIdx.x] = 0;
    __syncthreads();
    int i = blockIdx.x * blockDim.x + threadIdx.x;
    if (i < NB) {
        float x = cls[((size_t)b * NB + i) * 3 + k];
        float s = 1.0f / (1.0f + expf(-x));
        if (s < SCORE_TH) s = -1.0f;
        g_scores[(size_t)t * NB + i] = s;
        atomicAdd(&sh[fkey(s) >> 24], 1u);
    }
    __syncthreads();
    if (threadIdx.x < 256 && sh[threadIdx.x])
        atomicAdd(&g_hist[t][threadIdx.x], sh[threadIdx.x]);
}

// pick digit of current radix pass; update prefix & remaining-k; zero hist
__global__ void k_select(int shift) {
    int t = blockIdx.x;
    if (threadIdx.x == 0) {
        unsigned krem = g_krem[t];
        unsigned c = 0;
        for (int d = 255; d >= 0; --d) {
            unsigned h = g_hist[t][d];
            if (c + h >= krem) {
                g_krem[t]   = krem - c;
                g_prefix[t] |= ((unsigned)d) << shift;
                break;
            }
            c += h;
        }
    }
    __syncthreads();
    for (int i = threadIdx.x; i < 256; i += blockDim.x) g_hist[t][i] = 0;
}

// histogram of byte at `shift` restricted to elements matching the prefix
__global__ void k_hist(int shift) {
    int t = blockIdx.y;
    __shared__ unsigned sh[256];
    if (threadIdx.x < 256) sh[threadIdx.x] = 0;
    __syncthreads();
    int i = blockIdx.x * blockDim.x + threadIdx.x;
    unsigned pm = 0xFFFFFFFFu << (shift + 8);
    unsigned pref = g_prefix[t];
    if (i < NB) {
        unsigned key = fkey(g_scores[(size_t)t * NB + i]);
        if ((key & pm) == pref) atomicAdd(&sh[(key >> shift) & 255u], 1u);
    }
    __syncthreads();
    if (threadIdx.x < 256 && sh[threadIdx.x])
        atomicAdd(&g_hist[t][threadIdx.x], sh[threadIdx.x]);
}

// gather every element with key >= exact 512th-largest key
__global__ void k_gather() {
    int t = blockIdx.y;
    int i = blockIdx.x * blockDim.x + threadIdx.x;
    if (i >= NB) return;
    unsigned key = fkey(g_scores[(size_t)t * NB + i]);
    if (key >= g_prefix[t]) {
        unsigned pos = atomicAdd(&g_candCnt[t], 1u);
        if (pos < CAND_CAP)
            g_cand[t][pos] = ((unsigned long long)key << 32) | (unsigned)(~i);
    }
}

// single-block bitonic sort of candidates; emit top-512 (value desc, idx asc);
// fused: gather boxes and precompute corners/z/volume
__global__ void k_sort_prep(const float* __restrict__ boxes) {
    int t = blockIdx.x;
    int b = t / 3;
    __shared__ unsigned long long arr[CAND_CAP];
    unsigned cnt = g_candCnt[t];
    if (cnt > CAND_CAP) cnt = CAND_CAP;
    for (int i = threadIdx.x; i < CAND_CAP; i += blockDim.x)
        arr[i] = (i < (int)cnt) ? g_cand[t][i] : 0ULL;
    __syncthreads();
    // ascending bitonic sort
    for (unsigned ksz = 2; ksz <= CAND_CAP; ksz <<= 1) {
        for (unsigned j = ksz >> 1; j > 0; j >>= 1) {
            for (unsigned i = threadIdx.x; i < CAND_CAP; i += blockDim.x) {
                unsigned ixj = i ^ j;
                if (ixj > i) {
                    unsigned long long va = arr[i], vb = arr[ixj];
                    bool up = ((i & ksz) == 0);
                    if ((up && va > vb) || (!up && va < vb)) {
                        arr[i] = vb; arr[ixj] = va;
                    }
                }
            }
            __syncthreads();
        }
    }
    if (threadIdx.x < NPRE) {
        int r = threadIdx.x;
        unsigned long long v = arr[CAND_CAP - 1 - r]; // r-th largest
        unsigned key = (unsigned)(v >> 32);
        int idx = (int)(~(unsigned)(v & 0xFFFFFFFFu));
        float sc = finv(key);
        g_topIdx[t][r]   = idx;
        g_topScore[t][r] = sc;
        const float* bx = boxes + ((size_t)b * NB + idx) * 7;
        float x = bx[0], y = bx[1], z = bx[2];
        float dx = bx[3], dy = bx[4], dz = bx[5], rot = bx[6];
        float c = cosf(rot), s = sinf(rot);
        float hx = 0.5f * dx, hy = 0.5f * dy;
        Prep p;
        p.cx[0] = x + hx * c - hy * s;  p.cy[0] = y + hx * s + hy * c;
        p.cx[1] = x - hx * c - hy * s;  p.cy[1] = y - hx * s + hy * c;
        p.cx[2] = x - hx * c + hy * s;  p.cy[2] = y - hx * s - hy * c;
        p.cx[3] = x + hx * c + hy * s;  p.cy[3] = y + hx * s - hy * c;
        p.z0 = z - 0.5f * dz;  p.z1 = z + 0.5f * dz;
        p.vol = dx * dy * dz;  p.pad = 0.f;
        g_prep[t][r] = p;
    }
}

// exact rotated-rect intersection via Sutherland–Hodgman quad clipping
__device__ bool iou_over(const Prep& a, const Prep& b) {
    float h = fminf(a.z1, b.z1) - fmaxf(a.z0, b.z0);
    if (h <= 0.0f) return false;
    float px[10], py[10], qx[10], qy[10];
    int n = 4;
#pragma unroll
    for (int v = 0; v < 4; v++) { px[v] = a.cx[v]; py[v] = a.cy[v]; }
#pragma unroll
    for (int e = 0; e < 4; e++) {
        if (n == 0) break;
        float ex = b.cx[e], ey = b.cy[e];
        float dx_ = b.cx[(e + 1) & 3] - ex;
        float dy_ = b.cy[(e + 1) & 3] - ey;
        int m = 0;
        float fx = px[n - 1], fy = py[n - 1];
        float dprev = dx_ * (fy - ey) - dy_ * (fx - ex);
        for (int v = 0; v < n; v++) {
            float cxv = px[v], cyv = py[v];
            float d = dx_ * (cyv - ey) - dy_ * (cxv - ex);
            if (dprev >= 0.0f) {
                if (d >= 0.0f) { qx[m] = cxv; qy[m] = cyv; m++; }
                else {
                    float tt = dprev / (dprev - d);
                    qx[m] = fx + tt * (cxv - fx);
                    qy[m] = fy + tt * (cyv - fy); m++;
                }
            } else if (d >= 0.0f) {
                float tt = dprev / (dprev - d);
                qx[m] = fx + tt * (cxv - fx);
                qy[m] = fy + tt * (cyv - fy); m++;
                qx[m] = cxv; qy[m] = cyv; m++;
            }
            fx = cxv; fy = cyv; dprev = d;
        }
        n = m;
        for (int v = 0; v < n; v++) { px[v] = qx[v]; py[v] = qy[v]; }
    }
    if (n < 3) return false;
    float area = 0.0f;
    for (int v = 0; v < n; v++) {
        int w = (v + 1 == n) ? 0 : v + 1;
        area += px[v] * py[w] - px[w] * py[v];
    }
    area = 0.5f * fabsf(area);
    float i3 = area * h;
    float iou = i3 / fmaxf(a.vol + b.vol - i3, 1e-8f);
    return iou > NMS_TH;
}

// mask[t][i][w]: bit j set if IoU(i, j) > thresh
__global__ void k_iou(void) {
    int t = blockIdx.y, i = blockIdx.x;
    __shared__ float sA[12];
    if (threadIdx.x < 12)
        sA[threadIdx.x] = ((const float*)&g_prep[t][i])[threadIdx.x];
    __syncthreads();
    const Prep& A = *(const Prep*)sA;
    int lane = threadIdx.x & 31, wp = threadIdx.x >> 5;
#pragma unroll
    for (int it = 0; it < NPRE / 64; ++it) {
        int j = it * 64 + wp * 32 + lane;
        Prep B = g_prep[t][j];
        bool over = iou_over(A, B);
        unsigned m = __ballot_sync(0xFFFFFFFFu, over);
        if (lane == 0) g_mask[t][i][(it * 64 + wp * 32) >> 5] = m;
    }
}

// greedy suppression scan: warp holds 512-bit suppression state
__global__ void k_nms(void) {
    int t = blockIdx.x;
    __shared__ unsigned smask[NPRE * (NPRE / 32)];
    __shared__ float sscore[NPRE];
    const unsigned* gm = (const unsigned*)g_mask[t];
    for (int i = threadIdx.x; i < NPRE * (NPRE / 32); i += blockDim.x)
        smask[i] = gm[i];
    for (int i = threadIdx.x; i < NPRE; i += blockDim.x)
        sscore[i] = g_topScore[t][i];
    __syncthreads();
    if (threadIdx.x < 32) {
        int lane = threadIdx.x;
        unsigned sup = 0;
        for (int i = 0; i < NPRE; i++) {
            unsigned supw = __shfl_sync(0xFFFFFFFFu, sup, i >> 5);
            bool kept = (sscore[i] >= SCORE_TH) && !((supw >> (i & 31)) & 1u);
            if (kept && lane < 16) sup |= smask[i * 16 + lane];
            if (lane == 0) g_keep[t][i] = kept ? 1 : 0;
        }
    }
}

// write final padded outputs: boxes | scores | labels (flattened, float32)
__global__ void k_out(const float* __restrict__ boxes, float* __restrict__ out) {
    int t = blockIdx.x, b = t / 3, k = t % 3;
    __shared__ short rank[NPRE];
    if (threadIdx.x == 0) {
        int r = 0;
        for (int i = 0; i < NPRE; i++)
            rank[i] = g_keep[t][i] ? (short)(r++) : (short)-1;
    }
    __syncthreads();
    const int TOTAL = 3 * NPOST;               // 300 per batch
    float* outB = out;                          // (B, 300, 7)
    float* outS = out + 2 * TOTAL * 7;          // (B, 300)
    float* outL = out + 2 * TOTAL * 7 + 2 * TOTAL; // (B, 300)
    int baseRow = b * TOTAL + k * NPOST;
    for (int i = threadIdx.x; i < NPOST * 7; i += blockDim.x)
        outB[baseRow * 7 + i] = 0.0f;
    for (int i = threadIdx.x; i < NPOST; i += blockDim.x) {
        outS[baseRow + i] = 0.0f;
        outL[baseRow + i] = 0.0f;
    }
    __syncthreads();
    for (int i = threadIdx.x; i < NPRE; i += blockDim.x) {
        int r = rank[i];
        if (r >= 0 && r < NPOST) {
            int idx = g_topIdx[t][i];
            const float* bx = boxes + ((size_t)b * NB + idx) * 7;
            float* ob = outB + (baseRow + r) * 7;
#pragma unroll
            for (int c = 0; c < 7; c++) ob[c] = bx[c];
            outS[baseRow + r] = g_topScore[t][i];
            outL[baseRow + r] = (float)(k + 1);
        }
    }
}

// ---------------- launch -----------------------------------------------------
extern "C" void kernel_launch(void* const* d_in, const int* in_sizes, int n_in,
                              void* d_out, int out_size) {
    const float* cls   = (const float*)d_in[0];
    const float* boxes = (const float*)d_in[1];
    float* out = (float*)d_out;

    dim3 gscan(SCAN_BLOCKS, NT);

    k_init<<<NT, 256>>>();
    k_score_hist0<<<gscan, 256>>>(cls);
    k_select<<<NT, 256>>>(24);
    k_hist<<<gscan, 256>>>(16);
    k_select<<<NT, 256>>>(16);
    k_hist<<<gscan, 256>>>(8);
    k_select<<<NT, 256>>>(8);
    k_hist<<<gscan, 256>>>(0);
    k_select<<<NT, 256>>>(0);
    k_gather<<<gscan, 256>>>();
    k_sort_prep<<<NT, 1024>>>(boxes);
    k_iou<<<dim3(NPRE, NT), 64>>>();
    k_nms<<<NT, 256>>>();
    k_out<<<NT, 128>>>(boxes, out);
}

// round 17
// speedup vs baseline: 1.0108x; 1.0015x over previous
#include <cuda_runtime.h>
#include <math.h>

#define NB 100000
#define NT 6            // 2 batches x 3 classes
#define NPRE 512
#define NPOST 100
#define SCORE_TH 0.1f
#define NMS_TH 0.25f
#define CAND_CAP 4096
#define SCAN_BLOCKS ((NB + 255) / 256)

// ---------------- scratch (static device globals; no allocation) -------------
__device__ float         g_scores[NT * NB];
__device__ unsigned      g_hist[NT][256];
__device__ unsigned      g_prefix[NT];
__device__ unsigned      g_krem[NT];
__device__ unsigned long long g_cand[NT][CAND_CAP];
__device__ unsigned      g_candCnt[NT];
__device__ int           g_topIdx[NT][NPRE];
__device__ float         g_topScore[NT][NPRE];

struct Prep {
    float cx[4], cy[4];
    float z0, z1, vol, pad;
};
__device__ Prep          g_prep[NT][NPRE];
__device__ unsigned      g_mask[NT][NPRE][NPRE / 32];
__device__ unsigned char g_keep[NT][NPRE];

// monotone float -> uint key
__device__ __forceinline__ unsigned fkey(float f) {
    unsigned u = __float_as_uint(f);
    return (u & 0x80000000u) ? ~u : (u | 0x80000000u);
}
__device__ __forceinline__ float finv(unsigned k) {
    return __uint_as_float((k & 0x80000000u) ? (k ^ 0x80000000u) : ~k);
}

// ---------------- kernels ----------------------------------------------------

__global__ void k_init() {
    int t = blockIdx.x;
    for (int i = threadIdx.x; i < 256; i += blockDim.x) g_hist[t][i] = 0;
    if (threadIdx.x == 0) {
        g_prefix[t]  = 0;
        g_krem[t]    = NPRE;
        g_candCnt[t] = 0;
    }
}

// compute sigmoid scores + histogram of top byte (radix pass 0)
__global__ void k_score_hist0(const float* __restrict__ cls) {
    int t = blockIdx.y;
    int b = t / 3, k = t % 3;
    __shared__ unsigned sh[256];
    if (threadIdx.x < 256) sh[threadIdx.x] = 0;
    __syncthreads();
    int i = blockIdx.x * blockDim.x + threadIdx.x;
    if (i < NB) {
        float x = cls[((size_t)b * NB + i) * 3 + k];
        float s = 1.0f / (1.0f + expf(-x));
        if (s < SCORE_TH) s = -1.0f;
        g_scores[(size_t)t * NB + i] = s;
        atomicAdd(&sh[fkey(s) >> 24], 1u);
    }
    __syncthreads();
    if (threadIdx.x < 256 && sh[threadIdx.x])
        atomicAdd(&g_hist[t][threadIdx.x], sh[threadIdx.x]);
}

// pick digit of current radix pass; update prefix & remaining-k; zero hist
__global__ void k_select(int shift) {
    int t = blockIdx.x;
    if (threadIdx.x == 0) {
        unsigned krem = g_krem[t];
        unsigned c = 0;
        for (int d = 255; d >= 0; --d) {
            unsigned h = g_hist[t][d];
            if (c + h >= krem) {
                g_krem[t]   = krem - c;
                g_prefix[t] |= ((unsigned)d) << shift;
                break;
            }
            c += h;
        }
    }
    __syncthreads();
    for (int i = threadIdx.x; i < 256; i += blockDim.x) g_hist[t][i] = 0;
}

// histogram of byte at `shift` restricted to elements matching the prefix
__global__ void k_hist(int shift) {
    int t = blockIdx.y;
    __shared__ unsigned sh[256];
    if (threadIdx.x < 256) sh[threadIdx.x] = 0;
    __syncthreads();
    int i = blockIdx.x * blockDim.x + threadIdx.x;
    unsigned pm = 0xFFFFFFFFu << (shift + 8);
    unsigned pref = g_prefix[t];
    if (i < NB) {
        unsigned key = fkey(g_scores[(size_t)t * NB + i]);
        if ((key & pm) == pref) atomicAdd(&sh[(key >> shift) & 255u], 1u);
    }
    __syncthreads();
    if (threadIdx.x < 256 && sh[threadIdx.x])
        atomicAdd(&g_hist[t][threadIdx.x], sh[threadIdx.x]);
}

// gather every element with key >= exact 512th-largest key
__global__ void k_gather() {
    int t = blockIdx.y;
    int i = blockIdx.x * blockDim.x + threadIdx.x;
    if (i >= NB) return;
    unsigned key = fkey(g_scores[(size_t)t * NB + i]);
    if (key >= g_prefix[t]) {
        unsigned pos = atomicAdd(&g_candCnt[t], 1u);
        if (pos < CAND_CAP)
            g_cand[t][pos] = ((unsigned long long)key << 32) | (unsigned)(~i);
    }
}

// single-block bitonic sort of candidates; emit top-512 (value desc, idx asc);
// fused: gather boxes and precompute corners/z/volume
__global__ void k_sort_prep(const float* __restrict__ boxes) {
    int t = blockIdx.x;
    int b = t / 3;
    __shared__ unsigned long long arr[CAND_CAP];
    unsigned cnt = g_candCnt[t];
    if (cnt > CAND_CAP) cnt = CAND_CAP;
    for (int i = threadIdx.x; i < CAND_CAP; i += blockDim.x)
        arr[i] = (i < (int)cnt) ? g_cand[t][i] : 0ULL;
    __syncthreads();
    // ascending bitonic sort
    for (unsigned ksz = 2; ksz <= CAND_CAP; ksz <<= 1) {
        for (unsigned j = ksz >> 1; j > 0; j >>= 1) {
            for (unsigned i = threadIdx.x; i < CAND_CAP; i += blockDim.x) {
                unsigned ixj = i ^ j;
                if (ixj > i) {
                    unsigned long long va = arr[i], vb = arr[ixj];
                    bool up = ((i & ksz) == 0);
                    if ((up && va > vb) || (!up && va < vb)) {
                        arr[i] = vb; arr[ixj] = va;
                    }
                }
            }
            __syncthreads();
        }
    }
    if (threadIdx.x < NPRE) {
        int r = threadIdx.x;
        unsigned long long v = arr[CAND_CAP - 1 - r]; // r-th largest
        unsigned key = (unsigned)(v >> 32);
        int idx = (int)(~(unsigned)(v & 0xFFFFFFFFu));
        float sc = finv(key);
        g_topIdx[t][r]   = idx;
        g_topScore[t][r] = sc;
        const float* bx = boxes + ((size_t)b * NB + idx) * 7;
        float x = bx[0], y = bx[1], z = bx[2];
        float dx = bx[3], dy = bx[4], dz = bx[5], rot = bx[6];
        float c = cosf(rot), s = sinf(rot);
        float hx = 0.5f * dx, hy = 0.5f * dy;
        Prep p;
        p.cx[0] = x + hx * c - hy * s;  p.cy[0] = y + hx * s + hy * c;
        p.cx[1] = x - hx * c - hy * s;  p.cy[1] = y - hx * s + hy * c;
        p.cx[2] = x - hx * c + hy * s;  p.cy[2] = y - hx * s - hy * c;
        p.cx[3] = x + hx * c + hy * s;  p.cy[3] = y + hx * s - hy * c;
        p.z0 = z - 0.5f * dz;  p.z1 = z + 0.5f * dz;
        p.vol = dx * dy * dz;  p.pad = 0.f;
        g_prep[t][r] = p;
    }
}

// exact rotated-rect intersection via Sutherland–Hodgman quad clipping
__device__ bool iou_over(const Prep& a, const Prep& b) {
    float h = fminf(a.z1, b.z1) - fmaxf(a.z0, b.z0);
    if (h <= 0.0f) return false;
    float px[10], py[10], qx[10], qy[10];
    int n = 4;
#pragma unroll
    for (int v = 0; v < 4; v++) { px[v] = a.cx[v]; py[v] = a.cy[v]; }
#pragma unroll
    for (int e = 0; e < 4; e++) {
        if (n == 0) break;
        float ex = b.cx[e], ey = b.cy[e];
        float dx_ = b.cx[(e + 1) & 3] - ex;
        float dy_ = b.cy[(e + 1) & 3] - ey;
        int m = 0;
        float fx = px[n - 1], fy = py[n - 1];
        float dprev = dx_ * (fy - ey) - dy_ * (fx - ex);
        for (int v = 0; v < n; v++) {
            float cxv = px[v], cyv = py[v];
            float d = dx_ * (cyv - ey) - dy_ * (cxv - ex);
            if (dprev >= 0.0f) {
                if (d >= 0.0f) { qx[m] = cxv; qy[m] = cyv; m++; }
                else {
                    float tt = dprev / (dprev - d);
                    qx[m] = fx + tt * (cxv - fx);
                    qy[m] = fy + tt * (cyv - fy); m++;
                }
            } else if (d >= 0.0f) {
                float tt = dprev / (dprev - d);
                qx[m] = fx + tt * (cxv - fx);
                qy[m] = fy + tt * (cyv - fy); m++;
                qx[m] = cxv; qy[m] = cyv; m++;
            }
            fx = cxv; fy = cyv; dprev = d;
        }
        n = m;
        for (int v = 0; v < n; v++) { px[v] = qx[v]; py[v] = qy[v]; }
    }
    if (n < 3) return false;
    float area = 0.0f;
    for (int v = 0; v < n; v++) {
        int w = (v + 1 == n) ? 0 : v + 1;
        area += px[v] * py[w] - px[w] * py[v];
    }
    area = 0.5f * fabsf(area);
    float i3 = area * h;
    float iou = i3 / fmaxf(a.vol + b.vol - i3, 1e-8f);
    return iou > NMS_TH;
}

// mask[t][i][w]: bit j set if IoU(i, j) > thresh
__global__ void k_iou(void) {
    int t = blockIdx.y, i = blockIdx.x;
    __shared__ float sA[12];
    if (threadIdx.x < 12)
        sA[threadIdx.x] = ((const float*)&g_prep[t][i])[threadIdx.x];
    __syncthreads();
    const Prep& A = *(const Prep*)sA;
    int lane = threadIdx.x & 31, wp = threadIdx.x >> 5;
#pragma unroll
    for (int it = 0; it < NPRE / 64; ++it) {
        int j = it * 64 + wp * 32 + lane;
        Prep B = g_prep[t][j];
        bool over = iou_over(A, B);
        unsigned m = __ballot_sync(0xFFFFFFFFu, over);
        if (lane == 0) g_mask[t][i][(it * 64 + wp * 32) >> 5] = m;
    }
}

// greedy suppression scan: warp holds 512-bit suppression state
__global__ void k_nms(void) {
    int t = blockIdx.x;
    __shared__ unsigned smask[NPRE * (NPRE / 32)];
    __shared__ float sscore[NPRE];
    const unsigned* gm = (const unsigned*)g_mask[t];
    for (int i = threadIdx.x; i < NPRE * (NPRE / 32); i += blockDim.x)
        smask[i] = gm[i];
    for (int i = threadIdx.x; i < NPRE; i += blockDim.x)
        sscore[i] = g_topScore[t][i];
    __syncthreads();
    if (threadIdx.x < 32) {
        int lane = threadIdx.x;
        unsigned sup = 0;
        for (int i = 0; i < NPRE; i++) {
            unsigned supw = __shfl_sync(0xFFFFFFFFu, sup, i >> 5);
            bool kept = (sscore[i] >= SCORE_TH) && !((supw >> (i & 31)) & 1u);
            if (kept && lane < 16) sup |= smask[i * 16 + lane];
            if (lane == 0) g_keep[t][i] = kept ? 1 : 0;
        }
    }
}

// write final padded outputs: boxes | scores | labels (flattened, float32)
__global__ void k_out(const float* __restrict__ boxes, float* __restrict__ out) {
    int t = blockIdx.x, b = t / 3, k = t % 3;
    __shared__ short rank[NPRE];
    if (threadIdx.x == 0) {
        int r = 0;
        for (int i = 0; i < NPRE; i++)
            rank[i] = g_keep[t][i] ? (short)(r++) : (short)-1;
    }
    __syncthreads();
    const int TOTAL = 3 * NPOST;               // 300 per batch
    float* outB = out;                          // (B, 300, 7)
    float* outS = out + 2 * TOTAL * 7;          // (B, 300)
    float* outL = out + 2 * TOTAL * 7 + 2 * TOTAL; // (B, 300)
    int baseRow = b * TOTAL + k * NPOST;
    for (int i = threadIdx.x; i < NPOST * 7; i += blockDim.x)
        outB[baseRow * 7 + i] = 0.0f;
    for (int i = threadIdx.x; i < NPOST; i += blockDim.x) {
        outS[baseRow + i] = 0.0f;
        outL[baseRow + i] = 0.0f;
    }
    __syncthreads();
    for (int i = threadIdx.x; i < NPRE; i += blockDim.x) {
        int r = rank[i];
        if (r >= 0 && r < NPOST) {
            int idx = g_topIdx[t][i];
            const float* bx = boxes + ((size_t)b * NB + idx) * 7;
            float* ob = outB + (baseRow + r) * 7;
#pragma unroll
            for (int c = 0; c < 7; c++) ob[c] = bx[c];
            outS[baseRow + r] = g_topScore[t][i];
            outL[baseRow + r] = (float)(k + 1);
        }
    }
}

// ---------------- launch -----------------------------------------------------
extern "C" void kernel_launch(void* const* d_in, const int* in_sizes, int n_in,
                              void* d_out, int out_size) {
    const float* cls   = (const float*)d_in[0];
    const float* boxes = (const float*)d_in[1];
    float* out = (float*)d_out;

    dim3 gscan(SCAN_BLOCKS, NT);

    k_init<<<NT, 256>>>();
    k_score_hist0<<<gscan, 256>>>(cls);
    k_select<<<NT, 256>>>(24);
    k_hist<<<gscan, 256>>>(16);
    k_select<<<NT, 256>>>(16);
    k_hist<<<gscan, 256>>>(8);
    k_select<<<NT, 256>>>(8);
    k_hist<<<gscan, 256>>>(0);
    k_select<<<NT, 256>>>(0);
    k_gather<<<gscan, 256>>>();
    k_sort_prep<<<NT, 1024>>>(boxes);
    k_iou<<<dim3(NPRE, NT), 64>>>();
    k_nms<<<NT, 256>>>();
    k_out<<<NT, 128>>>(boxes, out);
}